// round 4
// baseline (speedup 1.0000x reference)
#include <cuda_runtime.h>
#include <math.h>

#define HDIM 32
#define NDIM 1024
#define BATCH 8
#define NT 512             // LUT resolution (proven err ~3e-7, budget 1e-3)
#define TILE 32
#define TPAIRS 528         // 32*33/2 upper-triangular tile pairs
#define NPAIRS (BATCH * TPAIRS)   // 4224

// LUT entry i = (0.5*f(i/NT), 0.5*f((i+1)/NT)); 0.5 symmetrization folded in.
__device__ float2 g_lut2[NT];

// ---------------------------------------------------------------------------
// Kernel 1: build LUT. One WARP per sample point.
// ---------------------------------------------------------------------------
__global__ void build_lut_kernel(const float* __restrict__ w1,
                                 const float* __restrict__ b1,
                                 const float* __restrict__ w2,
                                 const float* __restrict__ b2,
                                 const float* __restrict__ w3,
                                 const float* __restrict__ b3) {
    const int gwarp = (blockIdx.x * blockDim.x + threadIdx.x) >> 5;
    const int lane  = threadIdx.x & 31;
    if (gwarp > NT) return;

    const float x = (float)gwarp * (1.0f / (float)NT);
    float h1 = fmaxf(fmaf(x, w1[lane], b1[lane]), 0.0f);
    float s = b2[lane];
#pragma unroll
    for (int h = 0; h < HDIM; h++) {
        float h1h = __shfl_sync(0xffffffffu, h1, h);
        s = fmaf(h1h, w2[h * HDIM + lane], s);
    }
    float part = fmaxf(s, 0.0f) * w3[lane];
#pragma unroll
    for (int off = 16; off > 0; off >>= 1)
        part += __shfl_xor_sync(0xffffffffu, part, off);

    if (lane == 0) {
        float f = 0.5f / (1.0f + expf(-(part + b3[0])));   // 0.5 folded in
        if (gwarp < NT) g_lut2[gwarp].x     = f;
        if (gwarp > 0)  g_lut2[gwarp - 1].y = f;
    }
}

// ---------------------------------------------------------------------------
// Fused LUT lookup: one LDS.64 + interp. Returns 0.5*f(x).
// ---------------------------------------------------------------------------
__device__ __forceinline__ float lutf(const float2* __restrict__ slut, float x) {
    float u = x * (float)NT;
    int i = (int)u;
    i = min(max(i, 0), NT - 1);
    float2 v = slut[i];
    return fmaf(u - (float)i, v.y - v.x, v.x);
}

// ---------------------------------------------------------------------------
// Kernel 2: one (batch, ti<=tj) tile pair per block. Thread (r=tid>>3,
// q=tid&7) owns row r, float4 col group c0=4q. Stage (fA,fB) float2 pairs
// swizzled; one transposed LDS.64 per element serves BOTH output tiles:
//   fwd(r,c)    = fA[r][c] + fB[c][r]
//   mirror(r,c) = fB[r][c] + fA[c][r]
// ---------------------------------------------------------------------------
__global__ void __launch_bounds__(256)
corrector_kernel(const float* __restrict__ sim,
                 const int* __restrict__ masks,
                 float* __restrict__ out) {
    __shared__ float2 slut[NT];            // 4 KB
    __shared__ float2 sF[TILE * TILE];     // 8 KB: (fA, fB) swizzled
    __shared__ float  smi[TILE], smj[TILE];

    const int tid = threadIdx.x;
    const int r   = tid >> 3;
    const int c0  = (tid & 7) * 4;

    // unrank block -> (b, ti, tj)
    const int p = blockIdx.x;
    const int b = p / TPAIRS;
    int t = p - b * TPAIRS;
    int ti = (int)(0.5f * (65.0f - sqrtf(4225.0f - 8.0f * (float)t)));
    ti = min(max(ti, 0), 31);
    while (ti < 31 && (ti + 1) * (65 - (ti + 1)) / 2 <= t) ti++;
    while (ti > 0  && ti * (65 - ti) / 2 > t) ti--;
    const int tj = ti + (t - ti * (65 - ti) / 2);
    const bool diag = (ti == tj);

    const float* __restrict__ simb = sim + (size_t)b * (NDIM * NDIM);
    float*       __restrict__ outb = out + (size_t)b * (NDIM * NDIM);

    // stage LUT + masks (as float 0/1)
    slut[tid]       = g_lut2[tid];
    slut[tid + 256] = g_lut2[tid + 256];
    if (tid < TILE)          smi[tid]      = masks[b * NDIM + ti * TILE + tid] ? 1.0f : 0.0f;
    else if (tid < 2 * TILE) smj[tid - 32] = masks[b * NDIM + tj * TILE + (tid - 32)] ? 1.0f : 0.0f;

    // coalesced tile loads (overlap with barrier)
    float4 a4 = *(const float4*)(simb + (size_t)(ti * TILE + r) * NDIM + tj * TILE + c0);
    float4 b4 = diag ? a4
                     : *(const float4*)(simb + (size_t)(tj * TILE + r) * NDIM + ti * TILE + c0);
    __syncthreads();

    // 8 independent lookups
    float fA0 = lutf(slut, a4.x), fA1 = lutf(slut, a4.y);
    float fA2 = lutf(slut, a4.z), fA3 = lutf(slut, a4.w);
    float fB0 = lutf(slut, b4.x), fB1 = lutf(slut, b4.y);
    float fB2 = lutf(slut, b4.z), fB3 = lutf(slut, b4.w);

    // stage (fA,fB) swizzled: elem(row,col) -> row*32 + ((col+row)&31)
    sF[r * 32 + ((c0 + 0 + r) & 31)] = make_float2(fA0, fB0);
    sF[r * 32 + ((c0 + 1 + r) & 31)] = make_float2(fA1, fB1);
    sF[r * 32 + ((c0 + 2 + r) & 31)] = make_float2(fA2, fB2);
    sF[r * 32 + ((c0 + 3 + r) & 31)] = make_float2(fA3, fB3);
    __syncthreads();

    // transposed gather: sF[c][r] = (fA[c][r], fB[c][r])
    float2 p0 = sF[(c0 + 0) * 32 + ((r + c0 + 0) & 31)];
    float2 p1 = sF[(c0 + 1) * 32 + ((r + c0 + 1) & 31)];
    float2 p2 = sF[(c0 + 2) * 32 + ((r + c0 + 2) & 31)];
    float2 p3 = sF[(c0 + 3) * 32 + ((r + c0 + 3) & 31)];

    const float mi_r = smi[r], mj_r = smj[r];

    float4 vf;   // fwd tile (ti,tj) row r
    vf.x = (fA0 + p0.y) * (mi_r * smj[c0 + 0]);
    vf.y = (fA1 + p1.y) * (mi_r * smj[c0 + 1]);
    vf.z = (fA2 + p2.y) * (mi_r * smj[c0 + 2]);
    vf.w = (fA3 + p3.y) * (mi_r * smj[c0 + 3]);
    if (diag) {  // zero the global diagonal (only occurs in diagonal tiles)
        if (r == c0 + 0) vf.x = 0.0f;
        if (r == c0 + 1) vf.y = 0.0f;
        if (r == c0 + 2) vf.z = 0.0f;
        if (r == c0 + 3) vf.w = 0.0f;
    }
    *(float4*)(outb + (size_t)(ti * TILE + r) * NDIM + tj * TILE + c0) = vf;

    if (!diag) {
        float4 vm;  // mirror tile (tj,ti) row r
        vm.x = (fB0 + p0.x) * (mj_r * smi[c0 + 0]);
        vm.y = (fB1 + p1.x) * (mj_r * smi[c0 + 1]);
        vm.z = (fB2 + p2.x) * (mj_r * smi[c0 + 2]);
        vm.w = (fB3 + p3.x) * (mj_r * smi[c0 + 3]);
        *(float4*)(outb + (size_t)(tj * TILE + r) * NDIM + ti * TILE + c0) = vm;
    }
}

// ---------------------------------------------------------------------------
// Harness entry
// ---------------------------------------------------------------------------
extern "C" void kernel_launch(void* const* d_in, const int* in_sizes, int n_in,
                              void* d_out, int out_size) {
    const float* sim   = (const float*)d_in[0];
    const int*   masks = (const int*)d_in[1];
    const float* w1    = (const float*)d_in[2];
    const float* b1    = (const float*)d_in[3];
    const float* w2    = (const float*)d_in[4];
    const float* b2    = (const float*)d_in[5];
    const float* w3    = (const float*)d_in[6];
    const float* b3    = (const float*)d_in[7];
    float* out = (float*)d_out;

    build_lut_kernel<<<129, 128>>>(w1, b1, w2, b2, w3, b3);
    corrector_kernel<<<NPAIRS, 256>>>(sim, masks, out);
}

// round 5
// speedup vs baseline: 1.0015x; 1.0015x over previous
#include <cuda_runtime.h>
#include <cuda_fp16.h>
#include <math.h>

#define HDIM 32
#define NDIM 1024
#define BATCH 8
#define NT 256             // LUT resolution (interp err ~5e-6; fp16 quant dominates ~1e-4)
#define TILE 32
#define TPAIRS 528         // 32*33/2 upper-triangular tile pairs
#define NPAIRS (BATCH * TPAIRS)   // 4224 = 2112 blocks x 2 halves

// LUT entry i = (0.5*f(i/NT), 0.5*f((i+1)/NT)); 0.5 symmetrization folded in.
__device__ float2 g_lut2[NT];

// ---------------------------------------------------------------------------
// Kernel 1: build LUT. One WARP per sample point.
// ---------------------------------------------------------------------------
__global__ void build_lut_kernel(const float* __restrict__ w1,
                                 const float* __restrict__ b1,
                                 const float* __restrict__ w2,
                                 const float* __restrict__ b2,
                                 const float* __restrict__ w3,
                                 const float* __restrict__ b3) {
    const int gwarp = (blockIdx.x * blockDim.x + threadIdx.x) >> 5;
    const int lane  = threadIdx.x & 31;
    if (gwarp > NT) return;

    const float x = (float)gwarp * (1.0f / (float)NT);
    float h1 = fmaxf(fmaf(x, w1[lane], b1[lane]), 0.0f);
    float s = b2[lane];
#pragma unroll
    for (int h = 0; h < HDIM; h++) {
        float h1h = __shfl_sync(0xffffffffu, h1, h);
        s = fmaf(h1h, w2[h * HDIM + lane], s);
    }
    float part = fmaxf(s, 0.0f) * w3[lane];
#pragma unroll
    for (int off = 16; off > 0; off >>= 1)
        part += __shfl_xor_sync(0xffffffffu, part, off);

    if (lane == 0) {
        float f = 0.5f / (1.0f + expf(-(part + b3[0])));   // 0.5 folded in
        if (gwarp < NT) g_lut2[gwarp].x     = f;
        if (gwarp > 0)  g_lut2[gwarp - 1].y = f;
    }
}

// ---------------------------------------------------------------------------
// Fused LUT lookup: one random LDS.32 (half2) + fp32 interp. Returns 0.5*f(x).
// ---------------------------------------------------------------------------
__device__ __forceinline__ float lutf(const __half2* __restrict__ slut, float x) {
    float u = x * (float)NT;
    int i = (int)u;
    i = min(max(i, 0), NT - 1);
    float2 v = __half22float2(slut[i]);
    return fmaf(u - (float)i, v.y - v.x, v.x);
}

// ---------------------------------------------------------------------------
// Kernel 2: 512-thread blocks; each half-block (256 threads) handles one
// (batch, ti<=tj) tile pair, exactly as R4's proven inner loop:
//   fwd(r,c)    = fA[r][c] + fB[c][r]
//   mirror(r,c) = fB[r][c] + fA[c][r]
// with (fA,fB) staged once as swizzled float2 and one transposed LDS.64
// serving both outputs. Barriers now amortize over 2 pairs.
// ---------------------------------------------------------------------------
__global__ void __launch_bounds__(512)
corrector_kernel(const float* __restrict__ sim,
                 const int* __restrict__ masks,
                 float* __restrict__ out) {
    __shared__ __half2 slut[NT];               // 1 KB
    __shared__ float2  sF[2][TILE * TILE];     // 16 KB: (fA, fB) swizzled, per half
    __shared__ float   smi[2][TILE], smj[2][TILE];

    const int tid  = threadIdx.x;
    const int half = tid >> 8;
    const int htid = tid & 255;
    const int r    = htid >> 3;
    const int c0   = (htid & 7) * 4;

    // unrank this half's pair -> (b, ti, tj)
    const int p = blockIdx.x * 2 + half;
    const int b = p / TPAIRS;
    int t = p - b * TPAIRS;
    int ti = (int)(0.5f * (65.0f - sqrtf(4225.0f - 8.0f * (float)t)));
    ti = min(max(ti, 0), 31);
    while (ti < 31 && (ti + 1) * (65 - (ti + 1)) / 2 <= t) ti++;
    while (ti > 0  && ti * (65 - ti) / 2 > t) ti--;
    const int tj = ti + (t - ti * (65 - ti) / 2);
    const bool diag = (ti == tj);

    const float* __restrict__ simb = sim + (size_t)b * (NDIM * NDIM);
    float*       __restrict__ outb = out + (size_t)b * (NDIM * NDIM);

    // stage LUT (pack to half2) + masks (as float 0/1)
    if (tid < NT) {
        float2 v = g_lut2[tid];
        slut[tid] = __floats2half2_rn(v.x, v.y);
    }
    if (htid < TILE)          smi[half][htid]      = masks[b * NDIM + ti * TILE + htid] ? 1.0f : 0.0f;
    else if (htid < 2 * TILE) smj[half][htid - 32] = masks[b * NDIM + tj * TILE + (htid - 32)] ? 1.0f : 0.0f;

    // coalesced tile loads (overlap with barrier)
    float4 a4 = *(const float4*)(simb + (size_t)(ti * TILE + r) * NDIM + tj * TILE + c0);
    float4 b4 = diag ? a4
                     : *(const float4*)(simb + (size_t)(tj * TILE + r) * NDIM + ti * TILE + c0);
    __syncthreads();

    // 8 independent lookups
    float fA0 = lutf(slut, a4.x), fA1 = lutf(slut, a4.y);
    float fA2 = lutf(slut, a4.z), fA3 = lutf(slut, a4.w);
    float fB0 = lutf(slut, b4.x), fB1 = lutf(slut, b4.y);
    float fB2 = lutf(slut, b4.z), fB3 = lutf(slut, b4.w);

    // stage (fA,fB) swizzled: elem(row,col) -> row*32 + ((col+row)&31)
    float2* sFh = sF[half];
    sFh[r * 32 + ((c0 + 0 + r) & 31)] = make_float2(fA0, fB0);
    sFh[r * 32 + ((c0 + 1 + r) & 31)] = make_float2(fA1, fB1);
    sFh[r * 32 + ((c0 + 2 + r) & 31)] = make_float2(fA2, fB2);
    sFh[r * 32 + ((c0 + 3 + r) & 31)] = make_float2(fA3, fB3);
    __syncthreads();

    // transposed gather: sF[c][r] = (fA[c][r], fB[c][r])
    float2 p0 = sFh[(c0 + 0) * 32 + ((r + c0 + 0) & 31)];
    float2 p1 = sFh[(c0 + 1) * 32 + ((r + c0 + 1) & 31)];
    float2 p2 = sFh[(c0 + 2) * 32 + ((r + c0 + 2) & 31)];
    float2 p3 = sFh[(c0 + 3) * 32 + ((r + c0 + 3) & 31)];

    const float mi_r = smi[half][r], mj_r = smj[half][r];

    float4 vf;   // fwd tile (ti,tj) row r
    vf.x = (fA0 + p0.y) * (mi_r * smj[half][c0 + 0]);
    vf.y = (fA1 + p1.y) * (mi_r * smj[half][c0 + 1]);
    vf.z = (fA2 + p2.y) * (mi_r * smj[half][c0 + 2]);
    vf.w = (fA3 + p3.y) * (mi_r * smj[half][c0 + 3]);
    if (diag) {  // zero the global diagonal (only occurs in diagonal tiles)
        if (r == c0 + 0) vf.x = 0.0f;
        if (r == c0 + 1) vf.y = 0.0f;
        if (r == c0 + 2) vf.z = 0.0f;
        if (r == c0 + 3) vf.w = 0.0f;
    }
    *(float4*)(outb + (size_t)(ti * TILE + r) * NDIM + tj * TILE + c0) = vf;

    if (!diag) {
        float4 vm;  // mirror tile (tj,ti) row r
        vm.x = (fB0 + p0.x) * (mj_r * smi[half][c0 + 0]);
        vm.y = (fB1 + p1.x) * (mj_r * smi[half][c0 + 1]);
        vm.z = (fB2 + p2.x) * (mj_r * smi[half][c0 + 2]);
        vm.w = (fB3 + p3.x) * (mj_r * smi[half][c0 + 3]);
        *(float4*)(outb + (size_t)(tj * TILE + r) * NDIM + ti * TILE + c0) = vm;
    }
}

// ---------------------------------------------------------------------------
// Harness entry
// ---------------------------------------------------------------------------
extern "C" void kernel_launch(void* const* d_in, const int* in_sizes, int n_in,
                              void* d_out, int out_size) {
    const float* sim   = (const float*)d_in[0];
    const int*   masks = (const int*)d_in[1];
    const float* w1    = (const float*)d_in[2];
    const float* b1    = (const float*)d_in[3];
    const float* w2    = (const float*)d_in[4];
    const float* b2    = (const float*)d_in[5];
    const float* w3    = (const float*)d_in[6];
    const float* b3    = (const float*)d_in[7];
    float* out = (float*)d_out;

    build_lut_kernel<<<65, 128>>>(w1, b1, w2, b2, w3, b3);   // 257 warps needed, 260 launched
    corrector_kernel<<<NPAIRS / 2, 512>>>(sim, masks, out);
}

// round 6
// speedup vs baseline: 1.0137x; 1.0122x over previous
#include <cuda_runtime.h>
#include <cuda_fp16.h>
#include <math.h>

#define HDIM 32
#define NDIM 1024
#define BATCH 8
#define NT 256             // LUT resolution; fp16 quant dominates err (~1.8e-4, budget 1e-3)
#define TILE 32
#define TPAIRS 528         // 32*33/2 upper-triangular tile pairs
#define NPAIRS (BATCH * TPAIRS)   // 4224 = 2112 blocks x 2 halves

// LUT entry i = half2(0.5*f(i/NT), 0.5*f((i+1)/NT)); 0.5 symmetrization folded in.
__device__ __half2 g_lut_h2[NT];
// unrank table: t -> ti | (tj<<8)
__device__ int g_unrank[TPAIRS];

// ---------------------------------------------------------------------------
// Kernel 1: build LUT (one warp per sample) + unrank table (one thread per t).
// ---------------------------------------------------------------------------
__global__ void build_lut_kernel(const float* __restrict__ w1,
                                 const float* __restrict__ b1,
                                 const float* __restrict__ w2,
                                 const float* __restrict__ b2,
                                 const float* __restrict__ w3,
                                 const float* __restrict__ b3) {
    const int gtid  = blockIdx.x * blockDim.x + threadIdx.x;
    const int gwarp = gtid >> 5;
    const int lane  = threadIdx.x & 31;

    // unrank table
    if (gtid < TPAIRS) {
        int t = gtid, ti = 0;
        while (t >= TILE - ti) { t -= TILE - ti; ti++; }
        g_unrank[gtid] = ti | ((ti + t) << 8);
    }

    if (gwarp > NT) return;

    const float x = (float)gwarp * (1.0f / (float)NT);
    float h1 = fmaxf(fmaf(x, w1[lane], b1[lane]), 0.0f);
    float s = b2[lane];
#pragma unroll
    for (int h = 0; h < HDIM; h++) {
        float h1h = __shfl_sync(0xffffffffu, h1, h);
        s = fmaf(h1h, w2[h * HDIM + lane], s);
    }
    float part = fmaxf(s, 0.0f) * w3[lane];
#pragma unroll
    for (int off = 16; off > 0; off >>= 1)
        part += __shfl_xor_sync(0xffffffffu, part, off);

    if (lane == 0) {
        float f = 0.5f / (1.0f + expf(-(part + b3[0])));   // 0.5 folded in
        __half fh = __float2half_rn(f);
        __half* hp = (__half*)g_lut_h2;
        if (gwarp < NT) hp[2 * gwarp]     = fh;   // entry gwarp .x
        if (gwarp > 0)  hp[2 * gwarp - 1] = fh;   // entry gwarp-1 .y
    }
}

// ---------------------------------------------------------------------------
// LUT lookup, no clamp (x guaranteed in [0,1)): LDS.32 + fp32 interp.
// ---------------------------------------------------------------------------
__device__ __forceinline__ float lutf(const __half2* __restrict__ slut, float x) {
    float u = x * (float)NT;
    int i = (int)u;                       // 0..NT-1 by construction
    float2 v = __half22float2(slut[i]);
    return fmaf(u - (float)i, v.y - v.x, v.x);
}

// ---------------------------------------------------------------------------
// Kernel 2: 512-thread blocks; each 256-thread half handles one tile pair.
//   fwd(r,c)    = fA[r][c] + fB[c][r]
//   mirror(r,c) = fB[r][c] + fA[c][r]
// (fA,fB) staged once as XOR-swizzled float2; one transposed LDS.64 per
// element serves both output tiles.
// ---------------------------------------------------------------------------
__global__ void __launch_bounds__(512)
corrector_kernel(const float* __restrict__ sim,
                 const int* __restrict__ masks,
                 float* __restrict__ out) {
    __shared__ __half2 slut[NT];                         // 1 KB
    __shared__ float2  sF[2][TILE * TILE];               // 16 KB (fA,fB) swizzled
    __shared__ __align__(16) float smi[2][TILE];
    __shared__ __align__(16) float smj[2][TILE];

    const int tid  = threadIdx.x;
    const int half = tid >> 8;
    const int htid = tid & 255;
    const int r    = htid >> 3;
    const int c0   = (htid & 7) * 4;

    // pair lookup (table replaces arithmetic unranking)
    const int p = blockIdx.x * 2 + half;
    const int b = p / TPAIRS;
    const int code = __ldg(&g_unrank[p - b * TPAIRS]);
    const int ti = code & 255;
    const int tj = code >> 8;
    const bool diag = (ti == tj);

    const float* __restrict__ simb = sim + (size_t)b * (NDIM * NDIM);
    float*       __restrict__ outb = out + (size_t)b * (NDIM * NDIM);

    // stage LUT + masks (as float 0/1)
    if (tid < NT) slut[tid] = g_lut_h2[tid];
    if (htid < TILE)          smi[half][htid]      = (float)masks[b * NDIM + ti * TILE + htid];
    else if (htid < 2 * TILE) smj[half][htid - 32] = (float)masks[b * NDIM + tj * TILE + (htid - 32)];

    // coalesced tile loads (overlap with barrier)
    float4 a4 = *(const float4*)(simb + (size_t)(ti * TILE + r) * NDIM + tj * TILE + c0);
    float4 b4 = diag ? a4
                     : *(const float4*)(simb + (size_t)(tj * TILE + r) * NDIM + ti * TILE + c0);
    __syncthreads();

    // 8 independent lookups
    float fA0 = lutf(slut, a4.x), fA1 = lutf(slut, a4.y);
    float fA2 = lutf(slut, a4.z), fA3 = lutf(slut, a4.w);
    float fB0 = lutf(slut, b4.x), fB1 = lutf(slut, b4.y);
    float fB2 = lutf(slut, b4.z), fB3 = lutf(slut, b4.w);

    // XOR swizzle: elem(row,col) -> row*32 + (col^row).
    // store addrs: (r*32 + (c0^r)) ^ k   (disjoint low bits)
    float2* sFh = sF[half];
    const int sbase = r * 32 + (c0 ^ r);
    sFh[sbase ^ 0] = make_float2(fA0, fB0);
    sFh[sbase ^ 1] = make_float2(fA1, fB1);
    sFh[sbase ^ 2] = make_float2(fA2, fB2);
    sFh[sbase ^ 3] = make_float2(fA3, fB3);
    __syncthreads();

    // transposed gather: elem(c0+k, r) at (c0+k)*32 + (r^(c0+k)) = ((lbase)^k) + 32k
    const int lbase = c0 * 32 + (r ^ c0);
    float2 p0 = sFh[(lbase ^ 0)];
    float2 p1 = sFh[(lbase ^ 1) + 32];
    float2 p2 = sFh[(lbase ^ 2) + 64];
    float2 p3 = sFh[(lbase ^ 3) + 96];

    // masks: vectorized column loads, scalar row loads
    const float mi_r = smi[half][r], mj_r = smj[half][r];
    const float4 mj4 = *(const float4*)&smj[half][c0];
    const float4 mi4 = *(const float4*)&smi[half][c0];

    float4 vf;   // fwd tile (ti,tj) row r
    vf.x = (fA0 + p0.y) * (mi_r * mj4.x);
    vf.y = (fA1 + p1.y) * (mi_r * mj4.y);
    vf.z = (fA2 + p2.y) * (mi_r * mj4.z);
    vf.w = (fA3 + p3.y) * (mi_r * mj4.w);
    if (diag) {  // zero the global diagonal (only occurs in diagonal tiles)
        if (r == c0 + 0) vf.x = 0.0f;
        if (r == c0 + 1) vf.y = 0.0f;
        if (r == c0 + 2) vf.z = 0.0f;
        if (r == c0 + 3) vf.w = 0.0f;
    }
    *(float4*)(outb + (size_t)(ti * TILE + r) * NDIM + tj * TILE + c0) = vf;

    if (!diag) {
        float4 vm;  // mirror tile (tj,ti) row r
        vm.x = (fB0 + p0.x) * (mj_r * mi4.x);
        vm.y = (fB1 + p1.x) * (mj_r * mi4.y);
        vm.z = (fB2 + p2.x) * (mj_r * mi4.z);
        vm.w = (fB3 + p3.x) * (mj_r * mi4.w);
        *(float4*)(outb + (size_t)(tj * TILE + r) * NDIM + ti * TILE + c0) = vm;
    }
}

// ---------------------------------------------------------------------------
// Harness entry
// ---------------------------------------------------------------------------
extern "C" void kernel_launch(void* const* d_in, const int* in_sizes, int n_in,
                              void* d_out, int out_size) {
    const float* sim   = (const float*)d_in[0];
    const int*   masks = (const int*)d_in[1];
    const float* w1    = (const float*)d_in[2];
    const float* b1    = (const float*)d_in[3];
    const float* w2    = (const float*)d_in[4];
    const float* b2    = (const float*)d_in[5];
    const float* w3    = (const float*)d_in[6];
    const float* b3    = (const float*)d_in[7];
    float* out = (float*)d_out;

    build_lut_kernel<<<65, 128>>>(w1, b1, w2, b2, w3, b3);  // 8320 threads: LUT + unrank
    corrector_kernel<<<NPAIRS / 2, 512>>>(sim, masks, out);
}